// round 13
// baseline (speedup 1.0000x reference)
#include <cuda_runtime.h>
#include <math.h>

// Problem constants (fixed by the dataset)
#define NMAX 50000
#define HDIM 32
#define FIN  128
#define CDIM 16

// Scratch (device globals: allocation-free). Accessed ONLY from device code.
__device__ float g_deg [NMAX];
__device__ float g_dis [NMAX];
__device__ float g_xw1 [NMAX * HDIM];   // holds (x@W1) * dis[row]  (pre-scaled)
__device__ float g_agg1[NMAX * HDIM];
__device__ float g_xw2 [NMAX * HDIM];   // holds (h1@W2) * dis[row] (pre-scaled)
__device__ float g_agg2[NMAX * HDIM];

// ---------------------------------------------------------------------------
// K0: deg = 1.0 (self loop)
__global__ void k_deg_init(int n) {
    int i = blockIdx.x * blockDim.x + threadIdx.x;
    if (i < n) g_deg[i] = 1.0f;
}

// K1: deg[dst] += 1 per edge.
__global__ void __launch_bounds__(256)
k_deg_count(const int* __restrict__ ei, int E) {
    int e = blockIdx.x * blockDim.x + threadIdx.x;
    if (e < E) atomicAdd(&g_deg[ei[E + e]], 1.0f);
}

// K2: dis = rsqrt(deg)   (deg >= 1 always, so no zero guard needed)
__global__ void k_dis(int n) {
    int i = blockIdx.x * blockDim.x + threadIdx.x;
    if (i < n) g_dis[i] = rsqrtf(g_deg[i]);
}

// ---------------------------------------------------------------------------
// K3: acc = x @ W1 ; xw1 = acc*dis (pre-scaled for scatter);
//     agg1 = acc*dis^2 (self-loop init). Warp per row, lane = output column.
__global__ void __launch_bounds__(256)
k_gemm1(const float* __restrict__ x, const float* __restrict__ W1, int n) {
    __shared__ float Ws[FIN * HDIM];                 // 16 KB
    for (int i = threadIdx.x; i < FIN * HDIM; i += blockDim.x) Ws[i] = W1[i];
    __syncthreads();

    int row  = blockIdx.x * (blockDim.x >> 5) + (threadIdx.x >> 5);
    int lane = threadIdx.x & 31;
    if (row >= n) return;

    const float4* xr = (const float4*)(x + (size_t)row * FIN);
    float acc = 0.0f;
#pragma unroll 8
    for (int k4 = 0; k4 < FIN / 4; ++k4) {
        float4 xv = __ldg(&xr[k4]);
        int k = k4 * 4;
        acc = fmaf(xv.x, Ws[(k + 0) * HDIM + lane], acc);
        acc = fmaf(xv.y, Ws[(k + 1) * HDIM + lane], acc);
        acc = fmaf(xv.z, Ws[(k + 2) * HDIM + lane], acc);
        acc = fmaf(xv.w, Ws[(k + 3) * HDIM + lane], acc);
    }

    float d = g_dis[row];
    float s = acc * d;
    g_xw1 [row * HDIM + lane] = s;       // pre-scaled by dis[src]
    g_agg1[row * HDIM + lane] = s * d;   // self-loop: acc * dis^2
}

// ---------------------------------------------------------------------------
// K4/K6: edge scatter. 8 threads per edge, each thread handles 4 features:
//   v = xw_scaled[src] * dis[dst]  ->  4x atomicAdd (RED) into agg[dst].
// LAYER selects the global buffers IN DEVICE CODE (never pass __device__
// symbols as host-side kernel arguments — their host address is invalid).
template<int LAYER>
__global__ void __launch_bounds__(256)
k_scatter(const int* __restrict__ ei, int E) {
    const float* xw  = (LAYER == 1) ? g_xw1  : g_xw2;
    float*       agg = (LAYER == 1) ? g_agg1 : g_agg2;

    int t   = blockIdx.x * blockDim.x + threadIdx.x;
    int e   = t >> 3;          // edge index
    int sub = t & 7;           // which float4 of the 32-float row
    if (e >= E) return;

    int src = ei[e];           // row 0 of edge_index (8 adjacent lanes share sector)
    int dst = ei[E + e];       // row 1
    float dd = g_dis[dst];     // dis[src] already folded into xw

    const float4* xrow = (const float4*)(xw + (size_t)src * HDIM);
    float4 v = __ldg(&xrow[sub]);

    float* a = agg + (size_t)dst * HDIM + sub * 4;
    atomicAdd(a + 0, v.x * dd);
    atomicAdd(a + 1, v.y * dd);
    atomicAdd(a + 2, v.z * dd);
    atomicAdd(a + 3, v.w * dd);
}

// ---------------------------------------------------------------------------
// K5: h1 = tanh(agg1 + b1); acc = h1 @ W2; xw2 = acc*dis; agg2 = acc*dis^2.
// Warp per row; h1 row lives in the warp's lanes, GEMM via shuffles.
__global__ void __launch_bounds__(256)
k_layer2(const float* __restrict__ b1, const float* __restrict__ W2, int n) {
    __shared__ float Ws[HDIM * HDIM];                // 4 KB
    for (int i = threadIdx.x; i < HDIM * HDIM; i += blockDim.x) Ws[i] = W2[i];
    __syncthreads();

    int row  = blockIdx.x * (blockDim.x >> 5) + (threadIdx.x >> 5);
    int lane = threadIdx.x & 31;
    if (row >= n) return;

    float h = tanhf(g_agg1[row * HDIM + lane] + b1[lane]);
    float acc = 0.0f;
#pragma unroll
    for (int k = 0; k < HDIM; ++k) {
        float hk = __shfl_sync(0xffffffffu, h, k);
        acc = fmaf(hk, Ws[k * HDIM + lane], acc);
    }
    float d = g_dis[row];
    float s = acc * d;
    g_xw2 [row * HDIM + lane] = s;
    g_agg2[row * HDIM + lane] = s * d;
}

// ---------------------------------------------------------------------------
// K7: h2 = tanh(agg2 + b2); write h (2nd output, offset n*CDIM, if room);
//     out = h2 @ Wc + bc (1st output). Warp per row.
__global__ void __launch_bounds__(256)
k_final(const float* __restrict__ b2, const float* __restrict__ Wc,
        const float* __restrict__ bc, float* __restrict__ out, int n,
        int write_h) {
    __shared__ float Ws[HDIM * CDIM];                // 2 KB
    for (int i = threadIdx.x; i < HDIM * CDIM; i += blockDim.x) Ws[i] = Wc[i];
    __syncthreads();

    int row  = blockIdx.x * (blockDim.x >> 5) + (threadIdx.x >> 5);
    int lane = threadIdx.x & 31;
    if (row >= n) return;

    float h = tanhf(g_agg2[row * HDIM + lane] + b2[lane]);
    if (write_h)
        out[(size_t)n * CDIM + (size_t)row * HDIM + lane] = h;  // second output: h

    float acc = (lane < CDIM) ? bc[lane] : 0.0f;
#pragma unroll
    for (int k = 0; k < HDIM; ++k) {
        float hk = __shfl_sync(0xffffffffu, h, k);   // uniform across warp
        if (lane < CDIM) acc = fmaf(hk, Ws[k * CDIM + lane], acc);
    }
    if (lane < CDIM) out[(size_t)row * CDIM + lane] = acc;      // first output: logits
}

// ---------------------------------------------------------------------------
extern "C" void kernel_launch(void* const* d_in, const int* in_sizes, int n_in,
                              void* d_out, int out_size) {
    // Identify inputs by ELEMENT COUNT (robust to metadata ordering).
    // Unique sizes: x=6,400,000, ei=3,200,000, W1=4096, W2=1024, Wc=512,
    // bc=16; the two size-32 tensors are b1 then b2 in relative order.
    const float* x  = 0; const int* ei = 0;
    const float* W1 = 0; const float* b1 = 0;
    const float* W2 = 0; const float* b2 = 0;
    const float* Wc = 0; const float* bc = 0;
    int N = 0, E = 0;
    int bias_seen = 0;

    for (int i = 0; i < n_in; ++i) {
        int sz = in_sizes[i];
        if      (sz == 4096) W1 = (const float*)d_in[i];
        else if (sz == 1024) W2 = (const float*)d_in[i];
        else if (sz == 512)  Wc = (const float*)d_in[i];
        else if (sz == 16)   bc = (const float*)d_in[i];
        else if (sz == 32) {
            if (bias_seen == 0) b1 = (const float*)d_in[i];
            else                b2 = (const float*)d_in[i];
            ++bias_seen;
        }
        else if (sz >= 1000000) {
            if (sz == NMAX * FIN) { x = (const float*)d_in[i]; N = sz / FIN; }
            else                  { ei = (const int*)d_in[i];  E = sz / 2; }
        }
    }
    // Fallback to positional if size matching failed (shouldn't happen).
    if (!x)  { x  = (const float*)d_in[0]; N = in_sizes[0] / FIN; }
    if (!ei) { ei = (const int*)  d_in[1]; E = in_sizes[1] / 2; }
    if (!W1) W1 = (const float*)d_in[2];
    if (!b1) b1 = (const float*)d_in[3];
    if (!W2) W2 = (const float*)d_in[4];
    if (!b2) b2 = (const float*)d_in[5];
    if (!Wc) Wc = (const float*)d_in[6];
    if (!bc) bc = (const float*)d_in[7];

    float* out = (float*)d_out;
    int write_h = (out_size >= N * (CDIM + HDIM)) ? 1 : 0;

    const int TB = 256;
    int nodeBlocks1d = (N + TB - 1) / TB;
    int edgeBlocks1d = (E + TB - 1) / TB;
    int nodeWarpBlks = (N + (TB / 32) - 1) / (TB / 32);
    long long tOct = (long long)E * 8;
    int edgeOctBlks  = (int)((tOct + TB - 1) / TB);   // 8 threads per edge

    k_deg_init  <<<nodeBlocks1d, TB>>>(N);
    k_deg_count <<<edgeBlocks1d, TB>>>(ei, E);
    k_dis       <<<nodeBlocks1d, TB>>>(N);

    k_gemm1     <<<nodeWarpBlks, TB>>>(x, W1, N);
    k_scatter<1><<<edgeOctBlks,  TB>>>(ei, E);

    k_layer2    <<<nodeWarpBlks, TB>>>(b1, W2, N);
    k_scatter<2><<<edgeOctBlks,  TB>>>(ei, E);

    k_final     <<<nodeWarpBlks, TB>>>(b2, Wc, bc, out, N, write_h);
}

// round 15
// speedup vs baseline: 1.8394x; 1.8394x over previous
#include <cuda_runtime.h>
#include <math.h>

// Problem constants (fixed by the dataset)
#define NMAX 50000
#define HDIM 32
#define FIN  128
#define CDIM 16

// Scratch (device globals: allocation-free). Accessed ONLY from device code.
__device__ float g_deg [NMAX];
__device__ float g_dis [NMAX];
__device__ float g_xw1 [NMAX * HDIM];   // holds (x@W1) * dis[row]  (pre-scaled)
__device__ float g_agg1[NMAX * HDIM];
__device__ float g_xw2 [NMAX * HDIM];   // holds (h1@W2) * dis[row] (pre-scaled)
__device__ float g_agg2[NMAX * HDIM];

// ---------------------------------------------------------------------------
// K0: deg = 1.0 (self loop)
__global__ void k_deg_init(int n) {
    int i = blockIdx.x * blockDim.x + threadIdx.x;
    if (i < n) g_deg[i] = 1.0f;
}

// K1: deg[dst] += 1 per edge.
__global__ void __launch_bounds__(256)
k_deg_count(const int* __restrict__ ei, int E) {
    int e = blockIdx.x * blockDim.x + threadIdx.x;
    if (e < E) atomicAdd(&g_deg[ei[E + e]], 1.0f);
}

// K2: dis = rsqrt(deg)   (deg >= 1 always, so no zero guard needed)
__global__ void k_dis(int n) {
    int i = blockIdx.x * blockDim.x + threadIdx.x;
    if (i < n) g_dis[i] = rsqrtf(g_deg[i]);
}

// ---------------------------------------------------------------------------
// K3: acc = x @ W1 ; xw1 = acc*dis (pre-scaled for scatter);
//     agg1 = acc*dis^2 (self-loop init).
// Warp per 4 ROWS (lane = output column): each Ws LDS value feeds 4 FMAs,
// cutting L1/LDS wavefronts 4x vs the 1-row version (which was L1-bound at
// 80.5% L1, 12.6% fma in the R13 profile).
__global__ void __launch_bounds__(256)
k_gemm1(const float* __restrict__ x, const float* __restrict__ W1, int n) {
    __shared__ float Ws[FIN * HDIM];                 // 16 KB
    for (int i = threadIdx.x; i < FIN * HDIM; i += blockDim.x) Ws[i] = W1[i];
    __syncthreads();

    int warp = blockIdx.x * (blockDim.x >> 5) + (threadIdx.x >> 5);
    int lane = threadIdx.x & 31;
    int r0 = warp * 4;
    if (r0 >= n) return;

    const float4* xr0 = (const float4*)(x + (size_t)(r0 + 0) * FIN);
    const float4* xr1 = (const float4*)(x + (size_t)(r0 + 1) * FIN);
    const float4* xr2 = (const float4*)(x + (size_t)(r0 + 2) * FIN);
    const float4* xr3 = (const float4*)(x + (size_t)(r0 + 3) * FIN);
    bool v1 = (r0 + 1) < n, v2 = (r0 + 2) < n, v3 = (r0 + 3) < n;

    float a0 = 0.f, a1 = 0.f, a2 = 0.f, a3 = 0.f;
#pragma unroll 4
    for (int k4 = 0; k4 < FIN / 4; ++k4) {
        float4 x0 = __ldg(&xr0[k4]);
        float4 x1 = v1 ? __ldg(&xr1[k4]) : make_float4(0.f, 0.f, 0.f, 0.f);
        float4 x2 = v2 ? __ldg(&xr2[k4]) : make_float4(0.f, 0.f, 0.f, 0.f);
        float4 x3 = v3 ? __ldg(&xr3[k4]) : make_float4(0.f, 0.f, 0.f, 0.f);
        int k = k4 * 4;
        float w0 = Ws[(k + 0) * HDIM + lane];
        float w1 = Ws[(k + 1) * HDIM + lane];
        float w2 = Ws[(k + 2) * HDIM + lane];
        float w3 = Ws[(k + 3) * HDIM + lane];
        a0 = fmaf(x0.x, w0, a0); a0 = fmaf(x0.y, w1, a0);
        a0 = fmaf(x0.z, w2, a0); a0 = fmaf(x0.w, w3, a0);
        a1 = fmaf(x1.x, w0, a1); a1 = fmaf(x1.y, w1, a1);
        a1 = fmaf(x1.z, w2, a1); a1 = fmaf(x1.w, w3, a1);
        a2 = fmaf(x2.x, w0, a2); a2 = fmaf(x2.y, w1, a2);
        a2 = fmaf(x2.z, w2, a2); a2 = fmaf(x2.w, w3, a2);
        a3 = fmaf(x3.x, w0, a3); a3 = fmaf(x3.y, w1, a3);
        a3 = fmaf(x3.z, w2, a3); a3 = fmaf(x3.w, w3, a3);
    }

    {
        float d = g_dis[r0];
        float s = a0 * d;
        g_xw1 [(size_t)r0 * HDIM + lane] = s;
        g_agg1[(size_t)r0 * HDIM + lane] = s * d;
    }
    if (v1) { float d = g_dis[r0+1]; float s = a1 * d;
              g_xw1 [(size_t)(r0+1) * HDIM + lane] = s;
              g_agg1[(size_t)(r0+1) * HDIM + lane] = s * d; }
    if (v2) { float d = g_dis[r0+2]; float s = a2 * d;
              g_xw1 [(size_t)(r0+2) * HDIM + lane] = s;
              g_agg1[(size_t)(r0+2) * HDIM + lane] = s * d; }
    if (v3) { float d = g_dis[r0+3]; float s = a3 * d;
              g_xw1 [(size_t)(r0+3) * HDIM + lane] = s;
              g_agg1[(size_t)(r0+3) * HDIM + lane] = s * d; }
}

// ---------------------------------------------------------------------------
// K4/K6: edge scatter. 8 threads per edge, each thread handles 4 features:
//   v = xw_scaled[src] * dis[dst]  ->  red.global.add.v4.f32 into agg[dst].
// LAYER selects the global buffers IN DEVICE CODE.
template<int LAYER>
__global__ void __launch_bounds__(256)
k_scatter(const int* __restrict__ ei, int E) {
    const float* xw  = (LAYER == 1) ? g_xw1  : g_xw2;
    float*       agg = (LAYER == 1) ? g_agg1 : g_agg2;

    int t   = blockIdx.x * blockDim.x + threadIdx.x;
    int e   = t >> 3;          // edge index
    int sub = t & 7;           // which float4 of the 32-float row
    if (e >= E) return;

    int src = ei[e];           // row 0 of edge_index (8 adjacent lanes share sector)
    int dst = ei[E + e];       // row 1
    float dd = g_dis[dst];     // dis[src] already folded into xw

    const float4* xrow = (const float4*)(xw + (size_t)src * HDIM);
    float4 v = __ldg(&xrow[sub]);
    v.x *= dd; v.y *= dd; v.z *= dd; v.w *= dd;

    float4* a = (float4*)(agg + (size_t)dst * HDIM) + sub;
    asm volatile("red.global.add.v4.f32 [%0], {%1,%2,%3,%4};"
                 :: "l"(a), "f"(v.x), "f"(v.y), "f"(v.z), "f"(v.w)
                 : "memory");
}

// ---------------------------------------------------------------------------
// K5: h1 = tanh(agg1 + b1); acc = h1 @ W2; xw2 = acc*dis; agg2 = acc*dis^2.
// Warp per row; h1 row lives in the warp's lanes, GEMM via shuffles.
__global__ void __launch_bounds__(256)
k_layer2(const float* __restrict__ b1, const float* __restrict__ W2, int n) {
    __shared__ float Ws[HDIM * HDIM];                // 4 KB
    for (int i = threadIdx.x; i < HDIM * HDIM; i += blockDim.x) Ws[i] = W2[i];
    __syncthreads();

    int row  = blockIdx.x * (blockDim.x >> 5) + (threadIdx.x >> 5);
    int lane = threadIdx.x & 31;
    if (row >= n) return;

    float h = tanhf(g_agg1[row * HDIM + lane] + b1[lane]);
    float acc = 0.0f;
#pragma unroll
    for (int k = 0; k < HDIM; ++k) {
        float hk = __shfl_sync(0xffffffffu, h, k);
        acc = fmaf(hk, Ws[k * HDIM + lane], acc);
    }
    float d = g_dis[row];
    float s = acc * d;
    g_xw2 [row * HDIM + lane] = s;
    g_agg2[row * HDIM + lane] = s * d;
}

// ---------------------------------------------------------------------------
// K7: h2 = tanh(agg2 + b2); write h (2nd output, offset n*CDIM, if room);
//     out = h2 @ Wc + bc (1st output). Warp per row.
__global__ void __launch_bounds__(256)
k_final(const float* __restrict__ b2, const float* __restrict__ Wc,
        const float* __restrict__ bc, float* __restrict__ out, int n,
        int write_h) {
    __shared__ float Ws[HDIM * CDIM];                // 2 KB
    for (int i = threadIdx.x; i < HDIM * CDIM; i += blockDim.x) Ws[i] = Wc[i];
    __syncthreads();

    int row  = blockIdx.x * (blockDim.x >> 5) + (threadIdx.x >> 5);
    int lane = threadIdx.x & 31;
    if (row >= n) return;

    float h = tanhf(g_agg2[row * HDIM + lane] + b2[lane]);
    if (write_h)
        out[(size_t)n * CDIM + (size_t)row * HDIM + lane] = h;  // second output: h

    float acc = (lane < CDIM) ? bc[lane] : 0.0f;
#pragma unroll
    for (int k = 0; k < HDIM; ++k) {
        float hk = __shfl_sync(0xffffffffu, h, k);   // uniform across warp
        if (lane < CDIM) acc = fmaf(hk, Ws[k * CDIM + lane], acc);
    }
    if (lane < CDIM) out[(size_t)row * CDIM + lane] = acc;      // first output: logits
}

// ---------------------------------------------------------------------------
extern "C" void kernel_launch(void* const* d_in, const int* in_sizes, int n_in,
                              void* d_out, int out_size) {
    // Identify inputs by ELEMENT COUNT (robust to metadata ordering).
    const float* x  = 0; const int* ei = 0;
    const float* W1 = 0; const float* b1 = 0;
    const float* W2 = 0; const float* b2 = 0;
    const float* Wc = 0; const float* bc = 0;
    int N = 0, E = 0;
    int bias_seen = 0;

    for (int i = 0; i < n_in; ++i) {
        int sz = in_sizes[i];
        if      (sz == 4096) W1 = (const float*)d_in[i];
        else if (sz == 1024) W2 = (const float*)d_in[i];
        else if (sz == 512)  Wc = (const float*)d_in[i];
        else if (sz == 16)   bc = (const float*)d_in[i];
        else if (sz == 32) {
            if (bias_seen == 0) b1 = (const float*)d_in[i];
            else                b2 = (const float*)d_in[i];
            ++bias_seen;
        }
        else if (sz >= 1000000) {
            if (sz == NMAX * FIN) { x = (const float*)d_in[i]; N = sz / FIN; }
            else                  { ei = (const int*)d_in[i];  E = sz / 2; }
        }
    }
    if (!x)  { x  = (const float*)d_in[0]; N = in_sizes[0] / FIN; }
    if (!ei) { ei = (const int*)  d_in[1]; E = in_sizes[1] / 2; }
    if (!W1) W1 = (const float*)d_in[2];
    if (!b1) b1 = (const float*)d_in[3];
    if (!W2) W2 = (const float*)d_in[4];
    if (!b2) b2 = (const float*)d_in[5];
    if (!Wc) Wc = (const float*)d_in[6];
    if (!bc) bc = (const float*)d_in[7];

    float* out = (float*)d_out;
    int write_h = (out_size >= N * (CDIM + HDIM)) ? 1 : 0;

    const int TB = 256;
    int nodeBlocks1d = (N + TB - 1) / TB;
    int edgeBlocks1d = (E + TB - 1) / TB;
    int nodeWarpBlks = (N + (TB / 32) - 1) / (TB / 32);
    int quadWarpBlks = ((N + 3) / 4 + (TB / 32) - 1) / (TB / 32);  // warp = 4 rows
    long long tOct = (long long)E * 8;
    int edgeOctBlks  = (int)((tOct + TB - 1) / TB);   // 8 threads per edge

    k_deg_init  <<<nodeBlocks1d, TB>>>(N);
    k_deg_count <<<edgeBlocks1d, TB>>>(ei, E);
    k_dis       <<<nodeBlocks1d, TB>>>(N);

    k_gemm1     <<<quadWarpBlks, TB>>>(x, W1, N);
    k_scatter<1><<<edgeOctBlks,  TB>>>(ei, E);

    k_layer2    <<<nodeWarpBlks, TB>>>(b1, W2, N);
    k_scatter<2><<<edgeOctBlks,  TB>>>(ei, E);

    k_final     <<<nodeWarpBlks, TB>>>(b2, Wc, bc, out, N, write_h);
}